// round 7
// baseline (speedup 1.0000x reference)
#include <cuda_runtime.h>
#include <cstdint>

#define EPSV 1e-5f

// ---------------- scratch (device globals; no allocations allowed) ----------
__device__ float g_mid[3 * 4 * 8 * 512 * 512];
__device__ float g_qkv[3 * 4 * 512 * 512];
__device__ float g_ctx[4 * 512 * 512];

// ---------------- f32x2 helpers ---------------------------------------------
__device__ __forceinline__ unsigned long long pk2(float lo, float hi) {
    unsigned long long r;
    asm("mov.b64 %0, {%1, %2};" : "=l"(r) : "f"(lo), "f"(hi));
    return r;
}
__device__ __forceinline__ unsigned long long fma2(unsigned long long a,
                                                   unsigned long long b,
                                                   unsigned long long c) {
    unsigned long long d;
    asm("fma.rn.f32x2 %0, %1, %2, %3;" : "=l"(d) : "l"(a), "l"(b), "l"(c));
    return d;
}
union U2 { unsigned long long u[2]; float4 v; float f[4]; };

// ---------------- conv1: 1 -> 8 channels, 3x3 SAME, BN+ReLU folded ---------
__global__ void __launch_bounds__(256)
conv1_kernel(const float* __restrict__ xin, const float* __restrict__ w1,
             const float* __restrict__ b1, const float* __restrict__ g1,
             const float* __restrict__ be1, const float* __restrict__ m1,
             const float* __restrict__ v1, float* __restrict__ mid, int pbase)
{
    int z = blockIdx.z;
    int c = z & 7, b = (z >> 3) & 3, pl = z >> 5;
    int p = pbase + pl;
    int x = blockIdx.x * 64 + threadIdx.x;
    int y = blockIdx.y * 4 + threadIdx.y;
    int pc = p * 8 + c;
    float a  = g1[pc] * rsqrtf(v1[pc] + EPSV);
    float bb = be1[pc] + a * (b1[pc] - m1[pc]);
    const float* w  = w1 + pc * 9;
    const float* xb = xin + b * 262144;
    float s;
    if (x > 0 && x < 511 && y > 0 && y < 511) {
        const float* r0 = xb + (y - 1) * 512 + x;
        const float* r1 = r0 + 512;
        const float* r2 = r1 + 512;
        s = r0[-1] * w[0] + r0[0] * w[1] + r0[1] * w[2]
          + r1[-1] * w[3] + r1[0] * w[4] + r1[1] * w[5]
          + r2[-1] * w[6] + r2[0] * w[7] + r2[1] * w[8];
    } else {
        s = 0.f;
        #pragma unroll
        for (int ky = 0; ky < 3; ky++) {
            int yy = y + ky - 1;
            if (yy < 0 || yy > 511) continue;
            const float* row = xb + yy * 512;
            #pragma unroll
            for (int kx = 0; kx < 3; kx++) {
                int xx = x + kx - 1;
                if (xx < 0 || xx > 511) continue;
                s += row[xx] * w[ky * 3 + kx];
            }
        }
    }
    mid[(size_t)((pl * 4 + b) * 8 + c) * 262144 + y * 512 + x] = fmaxf(fmaf(a, s, bb), 0.f);
}

// ---------------- conv2: 8 -> 1 channel, 3x3 SAME, BN+ReLU folded ----------
__global__ void __launch_bounds__(256)
conv2_kernel(const float* __restrict__ mid, const float* __restrict__ w2,
             const float* __restrict__ b2, const float* __restrict__ g2,
             const float* __restrict__ be2, const float* __restrict__ m2,
             const float* __restrict__ v2, float* __restrict__ out, int pbase)
{
    __shared__ float tile[8][10][34];
    __shared__ float ws[72];
    int z = blockIdx.z;
    int b = z & 3, pl = z >> 2, p = pbase + pl;
    int tid = threadIdx.y * 32 + threadIdx.x;
    if (tid < 72) ws[tid] = w2[p * 72 + tid];
    float a  = g2[p] * rsqrtf(v2[p] + EPSV);
    float bb = be2[p] + a * (b2[p] - m2[p]);
    int x0 = blockIdx.x * 32, y0 = blockIdx.y * 8;
    const float* in = mid + (size_t)(pl * 4 + b) * 8 * 262144;
    for (int idx = tid; idx < 8 * 10 * 34; idx += 256) {
        int c = idx / 340, r = idx % 340, yy = r / 34, xx = r % 34;
        int gy = y0 + yy - 1, gx = x0 + xx - 1;
        float vv = 0.f;
        if (gy >= 0 && gy < 512 && gx >= 0 && gx < 512)
            vv = in[(size_t)c * 262144 + gy * 512 + gx];
        tile[c][yy][xx] = vv;
    }
    __syncthreads();
    int tx = threadIdx.x, ty = threadIdx.y;
    float s = 0.f;
    #pragma unroll
    for (int c = 0; c < 8; c++)
        #pragma unroll
        for (int ky = 0; ky < 3; ky++)
            #pragma unroll
            for (int kx = 0; kx < 3; kx++)
                s = fmaf(tile[c][ty + ky][tx + kx], ws[c * 9 + ky * 3 + kx], s);
    out[(size_t)(pl * 4 + b) * 262144 + (y0 + ty) * 512 + x0 + tx] = fmaxf(fmaf(a, s, bb), 0.f);
}

// ---------------- fused cross-head attention, v3 ----------------------------
// 512 threads, m-tile 64, 1 CTA/SM (216 KB smem), register-prefetch pipelined
// K/V chunk loads, split-column conflict-free LDS, f32x2 FMA throughout.
// smem (float offsets):
#define SSTR 516
#define OFF_KST 33024              // Ss [64][516]
#define OFF_QST 37152              // KsT [8][516]
#define OFF_VS  41504              // QsT [64][68]
#define OFF_CS  45856              // Vs  [64][68]
#define SMEM_WORDS 54048           // Cs  [2][64][64]

__global__ void __launch_bounds__(512, 1)
attn_kernel(const float* __restrict__ Q, const float* __restrict__ K,
            const float* __restrict__ V, float* __restrict__ attn_out,
            float* __restrict__ ctx)
{
    extern __shared__ float sm[];
    float* Ss  = sm;
    float* KsT = sm + OFF_KST;
    float* QsT = sm + OFF_QST;
    float* Vs  = sm + OFF_VS;
    float* Cs  = sm + OFF_CS;

    const int tid = threadIdx.x;
    const int b = blockIdx.z, i = blockIdx.y;
    const int m0 = blockIdx.x * 64;

    // zero ctx accumulators
    #pragma unroll
    for (int t = 0; t < 16; t++) Cs[tid + t * 512] = 0.f;

    // Q tile (64 x 64) transposed into QsT[k][row], prescaled by 1/8
    const float* Qb = Q + ((size_t)b * 512 + m0) * 512 + i * 64;
    #pragma unroll
    for (int t = 0; t < 8; t++) {
        int idx = tid + t * 512;
        int r = idx >> 6, k = idx & 63;
        QsT[k * 68 + r] = Qb[r * 512 + k] * 0.125f;
    }

    // S-gemm mapping: rows 8*rg..+7 ; cols 4*cg..+3 and 256+4*cg..+3
    const int rg = tid >> 6;
    const int cg = tid & 63;
    // ctx mapping: n-half, rows 4*crg..+3, cols ccol..+3
    const int half = tid >> 8;
    const int slot = tid & 255;
    const int crg  = slot >> 4;
    const int ccol = (slot & 15) * 4;
    // K/V staging thread roles
    const int kk = tid & 7, n0 = tid >> 3;      // K: 8 floats/thread/chunk

    const float* Kb = K + (size_t)b * 262144 + /*j*/ 0;   // rebased per j
    const float* Vbase = V + (size_t)b * 262144;

    float kreg[8], vreg[8];

    for (int j = 0; j < 8; j++) {
        const float* Kj = K + (size_t)b * 262144 + j * 64;
        const float* Vj = Vbase + j * 64;

        // prefetch K chunk 0
        #pragma unroll
        for (int t = 0; t < 8; t++) kreg[t] = Kj[(size_t)(n0 + 64 * t) * 512 + kk];

        unsigned long long acc2[8][4];
        #pragma unroll
        for (int ri = 0; ri < 8; ri++)
            #pragma unroll
            for (int cp = 0; cp < 4; cp++) acc2[ri][cp] = 0ull;

        for (int kc = 0; kc < 8; kc++) {
            __syncthreads();
            #pragma unroll
            for (int t = 0; t < 8; t++)
                KsT[kk * 516 + n0 + 64 * t] = kreg[t];
            __syncthreads();
            if (kc < 7) {
                int ka = (kc + 1) * 8 + kk;
                #pragma unroll
                for (int t = 0; t < 8; t++)
                    kreg[t] = Kj[(size_t)(n0 + 64 * t) * 512 + ka];
            }
            #pragma unroll
            for (int k = 0; k < 8; k++) {
                int kr = kc * 8 + k;
                U2 q0, q1, k0, k1;
                q0.v = *(const float4*)&QsT[kr * 68 + 8 * rg];
                q1.v = *(const float4*)&QsT[kr * 68 + 8 * rg + 4];
                k0.v = *(const float4*)&KsT[k * 516 + 4 * cg];
                k1.v = *(const float4*)&KsT[k * 516 + 256 + 4 * cg];
                unsigned long long kv[4] = { k0.u[0], k0.u[1], k1.u[0], k1.u[1] };
                float qs[8] = { q0.f[0], q0.f[1], q0.f[2], q0.f[3],
                                q1.f[0], q1.f[1], q1.f[2], q1.f[3] };
                #pragma unroll
                for (int ri = 0; ri < 8; ri++) {
                    unsigned long long qp = pk2(qs[ri], qs[ri]);
                    #pragma unroll
                    for (int cp = 0; cp < 4; cp++)
                        acc2[ri][cp] = fma2(qp, kv[cp], acc2[ri][cp]);
                }
            }
        }
        // store S: cols [4cg..+3] and [256+4cg..+3]
        #pragma unroll
        for (int ri = 0; ri < 8; ri++) {
            U2 s0, s1;
            s0.u[0] = acc2[ri][0]; s0.u[1] = acc2[ri][1];
            s1.u[0] = acc2[ri][2]; s1.u[1] = acc2[ri][3];
            *(float4*)&Ss[(8 * rg + ri) * SSTR + 4 * cg]       = s0.v;
            *(float4*)&Ss[(8 * rg + ri) * SSTR + 256 + 4 * cg] = s1.v;
        }

        // prefetch V chunk 0 (independent of softmax)
        #pragma unroll
        for (int t = 0; t < 8; t++) {
            int idx = tid + t * 512;
            int lr = idx >> 6, col = idx & 63;
            int n = (lr < 32) ? lr : (256 + lr - 32);
            vreg[t] = Vj[(size_t)n * 512 + col];
        }
        __syncthreads();

        // ---------- row softmax over n (512), write attn ----------
        {
            int w = tid >> 5, lane = tid & 31;
            float* ab = attn_out + ((((size_t)b * 8 + i) * 8 + j) * 512 + m0) * 512;
            for (int r = 4 * w; r < 4 * w + 4; r++) {
                float vals[16];
                float mx = -3.4e38f;
                #pragma unroll
                for (int t = 0; t < 16; t++) {
                    vals[t] = Ss[r * SSTR + lane + 32 * t];
                    mx = fmaxf(mx, vals[t]);
                }
                #pragma unroll
                for (int o = 16; o > 0; o >>= 1) mx = fmaxf(mx, __shfl_xor_sync(0xffffffffu, mx, o));
                float sum = 0.f;
                #pragma unroll
                for (int t = 0; t < 16; t++) { vals[t] = __expf(vals[t] - mx); sum += vals[t]; }
                #pragma unroll
                for (int o = 16; o > 0; o >>= 1) sum += __shfl_xor_sync(0xffffffffu, sum, o);
                float inv = 1.f / sum;
                #pragma unroll
                for (int t = 0; t < 16; t++) {
                    float pv = vals[t] * inv;
                    Ss[r * SSTR + lane + 32 * t] = pv;
                    __stcs(&ab[(size_t)r * 512 + lane + 32 * t], pv);
                }
            }
        }

        // ---------- ctx += P @ V (n-halves, f32x2 over n-pairs) ----------
        unsigned long long cacc[4][4];
        #pragma unroll
        for (int r = 0; r < 4; r++)
            #pragma unroll
            for (int c = 0; c < 4; c++) cacc[r][c] = 0ull;

        for (int vc = 0; vc < 8; vc++) {
            __syncthreads();   // Vs free + (vc==0) softmax done
            #pragma unroll
            for (int t = 0; t < 8; t++) {
                int idx = tid + t * 512;
                int lr = idx >> 6, col = idx & 63;
                Vs[lr * 68 + col] = vreg[t];
            }
            __syncthreads();
            if (vc < 7) {
                #pragma unroll
                for (int t = 0; t < 8; t++) {
                    int idx = tid + t * 512;
                    int lr = idx >> 6, col = idx & 63;
                    int n = (lr < 32) ? ((vc + 1) * 32 + lr)
                                      : (256 + (vc + 1) * 32 + lr - 32);
                    vreg[t] = Vj[(size_t)n * 512 + col];
                }
            }
            int nbase = half * 256 + vc * 32;
            #pragma unroll
            for (int np = 0; np < 16; np++) {
                int lb = half * 32 + np * 2;
                U2 v0, v1;
                v0.v = *(const float4*)&Vs[lb * 68 + ccol];
                v1.v = *(const float4*)&Vs[(lb + 1) * 68 + ccol];
                unsigned long long vp[4] = {
                    pk2(v0.f[0], v1.f[0]), pk2(v0.f[1], v1.f[1]),
                    pk2(v0.f[2], v1.f[2]), pk2(v0.f[3], v1.f[3]) };
                int n = nbase + np * 2;
                #pragma unroll
                for (int r = 0; r < 4; r++) {
                    unsigned long long pp =
                        *(const unsigned long long*)&Ss[(4 * crg + r) * SSTR + n];
                    #pragma unroll
                    for (int c = 0; c < 4; c++)
                        cacc[r][c] = fma2(pp, vp[c], cacc[r][c]);
                }
            }
        }
        // fold per-j partials (exclusive cells)
        #pragma unroll
        for (int r = 0; r < 4; r++)
            #pragma unroll
            for (int c = 0; c < 4; c++) {
                float2 un = *(float2*)&cacc[r][c];
                Cs[(size_t)half * 4096 + (4 * crg + r) * 64 + ccol + c] += un.x + un.y;
            }
    }
    __syncthreads();
    // combine halves, write ctx
    #pragma unroll
    for (int t = 0; t < 8; t++) {
        int idx = tid + t * 512;
        int r = idx >> 6, c = idx & 63;
        float vv = Cs[r * 64 + c] + Cs[4096 + r * 64 + c];
        ctx[((size_t)b * 512 + m0 + r) * 512 + i * 64 + c] = vv;
    }
}

// ---------------- launch ----------------------------------------------------
extern "C" void kernel_launch(void* const* d_in, const int* in_sizes, int n_in,
                              void* d_out, int out_size)
{
    const float* X   = (const float*)d_in[0];
    const float* w1  = (const float*)d_in[2];
    const float* b1  = (const float*)d_in[3];
    const float* g1  = (const float*)d_in[4];
    const float* be1 = (const float*)d_in[5];
    const float* m1  = (const float*)d_in[6];
    const float* v1  = (const float*)d_in[7];
    const float* w2  = (const float*)d_in[8];
    const float* b2  = (const float*)d_in[9];
    const float* g2  = (const float*)d_in[10];
    const float* be2 = (const float*)d_in[11];
    const float* m2  = (const float*)d_in[12];
    const float* v2  = (const float*)d_in[13];

    float* out  = (float*)d_out;
    float* attn = out + (size_t)4 * 512 * 512;

    float *mid, *qkv, *ctx;
    cudaGetSymbolAddress((void**)&mid, g_mid);
    cudaGetSymbolAddress((void**)&qkv, g_qkv);
    cudaGetSymbolAddress((void**)&ctx, g_ctx);

    const int SMEM = SMEM_WORDS * 4;  // 216192 B
    cudaFuncSetAttribute(attn_kernel, cudaFuncAttributeMaxDynamicSharedMemorySize, SMEM);

    dim3 cb1(64, 4), cb2(32, 8);

    conv1_kernel<<<dim3(8, 128, 96), cb1>>>(X, w1, b1, g1, be1, m1, v1, mid, 0);
    conv2_kernel<<<dim3(16, 64, 12), cb2>>>(mid, w2, b2, g2, be2, m2, v2, qkv, 0);

    attn_kernel<<<dim3(8, 8, 4), 512, SMEM>>>(qkv, qkv + 1048576, qkv + 2097152, attn, ctx);

    conv1_kernel<<<dim3(8, 128, 32), cb1>>>(ctx, w1, b1, g1, be1, m1, v1, mid, 3);
    conv2_kernel<<<dim3(16, 64, 4), cb2>>>(mid, w2, b2, g2, be2, m2, v2, out, 3);
}

// round 9
// speedup vs baseline: 1.4778x; 1.4778x over previous
#include <cuda_runtime.h>
#include <cuda_bf16.h>
#include <cstdint>

#define EPSV 1e-5f

__device__ float g_mid[3 * 4 * 8 * 512 * 512];
__device__ float g_qkv[3 * 4 * 512 * 512];
__device__ float g_ctx[4 * 512 * 512];

// ======================= conv kernels =======================================
__global__ void __launch_bounds__(256)
conv1_kernel(const float* __restrict__ xin, const float* __restrict__ w1,
             const float* __restrict__ b1, const float* __restrict__ g1,
             const float* __restrict__ be1, const float* __restrict__ m1,
             const float* __restrict__ v1, float* __restrict__ mid, int pbase)
{
    int z = blockIdx.z;
    int c = z & 7, b = (z >> 3) & 3, pl = z >> 5;
    int p = pbase + pl;
    int x = blockIdx.x * 64 + threadIdx.x;
    int y = blockIdx.y * 4 + threadIdx.y;
    int pc = p * 8 + c;
    float a  = g1[pc] * rsqrtf(v1[pc] + EPSV);
    float bb = be1[pc] + a * (b1[pc] - m1[pc]);
    const float* w  = w1 + pc * 9;
    const float* xb = xin + b * 262144;
    float s;
    if (x > 0 && x < 511 && y > 0 && y < 511) {
        const float* r0 = xb + (y - 1) * 512 + x;
        const float* r1 = r0 + 512;
        const float* r2 = r1 + 512;
        s = r0[-1] * w[0] + r0[0] * w[1] + r0[1] * w[2]
          + r1[-1] * w[3] + r1[0] * w[4] + r1[1] * w[5]
          + r2[-1] * w[6] + r2[0] * w[7] + r2[1] * w[8];
    } else {
        s = 0.f;
        #pragma unroll
        for (int ky = 0; ky < 3; ky++) {
            int yy = y + ky - 1;
            if (yy < 0 || yy > 511) continue;
            const float* row = xb + yy * 512;
            #pragma unroll
            for (int kx = 0; kx < 3; kx++) {
                int xx = x + kx - 1;
                if (xx < 0 || xx > 511) continue;
                s += row[xx] * w[ky * 3 + kx];
            }
        }
    }
    mid[(size_t)((pl * 4 + b) * 8 + c) * 262144 + y * 512 + x] = fmaxf(fmaf(a, s, bb), 0.f);
}

__global__ void __launch_bounds__(256)
conv2_kernel(const float* __restrict__ mid, const float* __restrict__ w2,
             const float* __restrict__ b2, const float* __restrict__ g2,
             const float* __restrict__ be2, const float* __restrict__ m2,
             const float* __restrict__ v2, float* __restrict__ out, int pbase)
{
    __shared__ float tile[8][10][34];
    __shared__ float ws[72];
    int z = blockIdx.z;
    int b = z & 3, pl = z >> 2, p = pbase + pl;
    int tid = threadIdx.y * 32 + threadIdx.x;
    if (tid < 72) ws[tid] = w2[p * 72 + tid];
    float a  = g2[p] * rsqrtf(v2[p] + EPSV);
    float bb = be2[p] + a * (b2[p] - m2[p]);
    int x0 = blockIdx.x * 32, y0 = blockIdx.y * 8;
    const float* in = mid + (size_t)(pl * 4 + b) * 8 * 262144;
    for (int idx = tid; idx < 8 * 10 * 34; idx += 256) {
        int c = idx / 340, r = idx % 340, yy = r / 34, xx = r % 34;
        int gy = y0 + yy - 1, gx = x0 + xx - 1;
        float vv = 0.f;
        if (gy >= 0 && gy < 512 && gx >= 0 && gx < 512)
            vv = in[(size_t)c * 262144 + gy * 512 + gx];
        tile[c][yy][xx] = vv;
    }
    __syncthreads();
    int tx = threadIdx.x, ty = threadIdx.y;
    float s = 0.f;
    #pragma unroll
    for (int c = 0; c < 8; c++)
        #pragma unroll
        for (int ky = 0; ky < 3; ky++)
            #pragma unroll
            for (int kx = 0; kx < 3; kx++)
                s = fmaf(tile[c][ty + ky][tx + kx], ws[c * 9 + ky * 3 + kx], s);
    out[(size_t)(pl * 4 + b) * 262144 + (y0 + ty) * 512 + x0 + tx] = fmaxf(fmaf(a, s, bb), 0.f);
}

// ======================= mma.sync helpers (sm_80+ baseline PTX) =============
__device__ __forceinline__ void mma_bf16(float d[4], const uint32_t a[4],
                                         const uint32_t b[2]) {
    asm volatile(
        "mma.sync.aligned.m16n8k16.row.col.f32.bf16.bf16.f32 "
        "{%0,%1,%2,%3}, {%4,%5,%6,%7}, {%8,%9}, {%0,%1,%2,%3};"
        : "+f"(d[0]), "+f"(d[1]), "+f"(d[2]), "+f"(d[3])
        : "r"(a[0]), "r"(a[1]), "r"(a[2]), "r"(a[3]), "r"(b[0]), "r"(b[1]));
}
__device__ __forceinline__ uint32_t pkbf(float lo, float hi) {
    __nv_bfloat162 t = __floats2bfloat162_rn(lo, hi);
    return *reinterpret_cast<uint32_t*>(&t);
}
// hi = bf16 truncation (exact upper 16 bits); pair packer from raw f32 bits
__device__ __forceinline__ uint32_t hipair(uint32_t u0, uint32_t u1) {
    return (u0 >> 16) | (u1 & 0xFFFF0000u);
}
__device__ __forceinline__ float hif(float x) {
    return __uint_as_float(__float_as_uint(x) & 0xFFFF0000u);
}

// smem byte offsets:  Ss[64][516] f32 | Qhi/Qlo[64][72] bf16 | Khi/Klo[128][72] bf16
#define SSTR 516
#define O_QHI 132096
#define O_QLO 141312
#define O_KHI 150528
#define O_KLO 168960
#define SMEMB 187392

// ======================= attention via mma.sync bf16 (hi/lo split) ==========
__global__ void __launch_bounds__(512, 1)
attn_mma_kernel(const float* __restrict__ Q, const float* __restrict__ K,
                const float* __restrict__ V, float* __restrict__ attn_out,
                float* __restrict__ ctx)
{
    extern __shared__ char smc[];
    float* Ss = (float*)smc;
    uint32_t* QHI = (uint32_t*)(smc + O_QHI);   // word-addressed, row stride 36
    uint32_t* QLO = (uint32_t*)(smc + O_QLO);
    uint32_t* KHI = (uint32_t*)(smc + O_KHI);   // 128 rows x 36 words
    uint32_t* KLO = (uint32_t*)(smc + O_KLO);
    uint32_t* PAH = KHI;                        // ctx aliases: P rows 0..63
    uint32_t* PAL = KLO;
    uint32_t* VTH = KHI + 64 * 36;              // V^T rows(d) 0..63
    uint32_t* VTL = KLO + 64 * 36;

    const int tid = threadIdx.x;
    const int w = tid >> 5, lane = tid & 31;
    const int g = lane >> 2, t = lane & 3;
    const int mb = w & 3, ns = w >> 2;          // warp tile: rows 16mb, col-group ns
    const int b = blockIdx.z, i = blockIdx.y, m0 = blockIdx.x * 64;

    // ---- Q tile: scale 1/8, hi/lo split ----
    const float* Qb = Q + ((size_t)b * 512 + m0) * 512 + i * 64;
    #pragma unroll
    for (int tt = 0; tt < 2; tt++) {
        int idx = tid + tt * 512, row = idx >> 4, k0 = (idx & 15) * 4;
        float4 v = *(const float4*)&Qb[(size_t)row * 512 + k0];
        v.x *= 0.125f; v.y *= 0.125f; v.z *= 0.125f; v.w *= 0.125f;
        uint32_t u0 = __float_as_uint(v.x), u1 = __float_as_uint(v.y);
        uint32_t u2 = __float_as_uint(v.z), u3 = __float_as_uint(v.w);
        int wi = row * 36 + (k0 >> 1);
        *(uint2*)&QHI[wi] = make_uint2(hipair(u0, u1), hipair(u2, u3));
        *(uint2*)&QLO[wi] = make_uint2(pkbf(v.x - hif(v.x), v.y - hif(v.y)),
                                       pkbf(v.z - hif(v.z), v.w - hif(v.w)));
    }

    float cacc[2][4];
    #pragma unroll
    for (int a2 = 0; a2 < 2; a2++)
        #pragma unroll
        for (int c2 = 0; c2 < 4; c2++) cacc[a2][c2] = 0.f;

    for (int j = 0; j < 8; j++) {
        const float* Kj = K + (size_t)b * 262144 + j * 64;
        const float* Vj = V + (size_t)b * 262144 + j * 64;

        // ================= S = Q K^T, 4 chunks of 128 n =================
        for (int nc = 0; nc < 4; nc++) {
            __syncthreads();
            #pragma unroll
            for (int tt = 0; tt < 4; tt++) {
                int idx = tid + tt * 512, n = idx >> 4, k0 = (idx & 15) * 4;
                float4 v = *(const float4*)&Kj[(size_t)(nc * 128 + n) * 512 + k0];
                uint32_t u0 = __float_as_uint(v.x), u1 = __float_as_uint(v.y);
                uint32_t u2 = __float_as_uint(v.z), u3 = __float_as_uint(v.w);
                int wi = n * 36 + (k0 >> 1);
                *(uint2*)&KHI[wi] = make_uint2(hipair(u0, u1), hipair(u2, u3));
                *(uint2*)&KLO[wi] = make_uint2(pkbf(v.x - hif(v.x), v.y - hif(v.y)),
                                               pkbf(v.z - hif(v.z), v.w - hif(v.w)));
            }
            __syncthreads();

            float sacc[4][4];
            #pragma unroll
            for (int nt = 0; nt < 4; nt++)
                #pragma unroll
                for (int c2 = 0; c2 < 4; c2++) sacc[nt][c2] = 0.f;

            #pragma unroll
            for (int kc = 0; kc < 4; kc++) {
                int ab = (16 * mb + g) * 36 + kc * 8 + t;
                uint32_t ah[4] = { QHI[ab], QHI[ab + 288], QHI[ab + 4], QHI[ab + 292] };
                uint32_t al[4] = { QLO[ab], QLO[ab + 288], QLO[ab + 4], QLO[ab + 292] };
                #pragma unroll
                for (int nt = 0; nt < 4; nt++) {
                    int bb = (32 * ns + 8 * nt + g) * 36 + kc * 8 + t;
                    uint32_t bh[2] = { KHI[bb], KHI[bb + 4] };
                    uint32_t bl[2] = { KLO[bb], KLO[bb + 4] };
                    mma_bf16(sacc[nt], ah, bh);
                    mma_bf16(sacc[nt], ah, bl);
                    mma_bf16(sacc[nt], al, bh);
                }
            }
            #pragma unroll
            for (int nt = 0; nt < 4; nt++) {
                int col = nc * 128 + 32 * ns + 8 * nt + 2 * t;
                *(float2*)&Ss[(16 * mb + g) * SSTR + col] =
                    make_float2(sacc[nt][0], sacc[nt][1]);
                *(float2*)&Ss[(16 * mb + g + 8) * SSTR + col] =
                    make_float2(sacc[nt][2], sacc[nt][3]);
            }
        }
        __syncthreads();

        // ================= softmax over n, write attn ====================
        {
            float* ab = attn_out + ((((size_t)b * 8 + i) * 8 + j) * 512 + m0) * 512;
            for (int r = 4 * w; r < 4 * w + 4; r++) {
                float vals[16];
                float mx = -3.4e38f;
                #pragma unroll
                for (int tt = 0; tt < 16; tt++) {
                    vals[tt] = Ss[r * SSTR + lane + 32 * tt];
                    mx = fmaxf(mx, vals[tt]);
                }
                #pragma unroll
                for (int o = 16; o > 0; o >>= 1)
                    mx = fmaxf(mx, __shfl_xor_sync(0xffffffffu, mx, o));
                float sum = 0.f;
                #pragma unroll
                for (int tt = 0; tt < 16; tt++) { vals[tt] = __expf(vals[tt] - mx); sum += vals[tt]; }
                #pragma unroll
                for (int o = 16; o > 0; o >>= 1)
                    sum += __shfl_xor_sync(0xffffffffu, sum, o);
                float inv = 1.f / sum;
                #pragma unroll
                for (int tt = 0; tt < 16; tt++) {
                    float pv = vals[tt] * inv;
                    Ss[r * SSTR + lane + 32 * tt] = pv;
                    __stcs(&ab[(size_t)r * 512 + lane + 32 * tt], pv);
                }
            }
        }

        // ================= ctx += P V, 8 chunks of 64 n ==================
        for (int vc = 0; vc < 8; vc++) {
            __syncthreads();
            // P chunk: Ss rows -> A layout (hi/lo)
            {
                int r = tid >> 3, n0 = (tid & 7) * 8;
                float4 p0 = *(const float4*)&Ss[r * SSTR + vc * 64 + n0];
                float4 p1 = *(const float4*)&Ss[r * SSTR + vc * 64 + n0 + 4];
                uint32_t a0 = __float_as_uint(p0.x), a1 = __float_as_uint(p0.y);
                uint32_t a2 = __float_as_uint(p0.z), a3 = __float_as_uint(p0.w);
                uint32_t a4 = __float_as_uint(p1.x), a5 = __float_as_uint(p1.y);
                uint32_t a6 = __float_as_uint(p1.z), a7 = __float_as_uint(p1.w);
                int wi = r * 36 + (n0 >> 1);
                *(uint4*)&PAH[wi] = make_uint4(hipair(a0, a1), hipair(a2, a3),
                                               hipair(a4, a5), hipair(a6, a7));
                *(uint4*)&PAL[wi] = make_uint4(
                    pkbf(p0.x - hif(p0.x), p0.y - hif(p0.y)),
                    pkbf(p0.z - hif(p0.z), p0.w - hif(p0.w)),
                    pkbf(p1.x - hif(p1.x), p1.y - hif(p1.y)),
                    pkbf(p1.z - hif(p1.z), p1.w - hif(p1.w)));
            }
            // V chunk: gmem [n][d] -> V^T[d][n] (hi/lo)
            {
                int d = tid & 63, nb0 = (tid >> 6) * 8;
                float vv[8];
                #pragma unroll
                for (int e = 0; e < 8; e++)
                    vv[e] = Vj[(size_t)(vc * 64 + nb0 + e) * 512 + d];
                uint32_t hw[4], lw[4];
                #pragma unroll
                for (int e = 0; e < 4; e++) {
                    hw[e] = hipair(__float_as_uint(vv[2 * e]), __float_as_uint(vv[2 * e + 1]));
                    lw[e] = pkbf(vv[2 * e] - hif(vv[2 * e]),
                                 vv[2 * e + 1] - hif(vv[2 * e + 1]));
                }
                int wi = d * 36 + (nb0 >> 1);
                *(uint4*)&VTH[wi] = make_uint4(hw[0], hw[1], hw[2], hw[3]);
                *(uint4*)&VTL[wi] = make_uint4(lw[0], lw[1], lw[2], lw[3]);
            }
            __syncthreads();
            #pragma unroll
            for (int kc = 0; kc < 4; kc++) {
                int ab = (16 * mb + g) * 36 + kc * 8 + t;
                uint32_t ah[4] = { PAH[ab], PAH[ab + 288], PAH[ab + 4], PAH[ab + 292] };
                uint32_t al[4] = { PAL[ab], PAL[ab + 288], PAL[ab + 4], PAL[ab + 292] };
                #pragma unroll
                for (int t2 = 0; t2 < 2; t2++) {
                    int bb = (8 * ns + 32 * t2 + g) * 36 + kc * 8 + t;
                    uint32_t bh[2] = { VTH[bb], VTH[bb + 4] };
                    uint32_t bl[2] = { VTL[bb], VTL[bb + 4] };
                    mma_bf16(cacc[t2], ah, bh);
                    mma_bf16(cacc[t2], ah, bl);
                    mma_bf16(cacc[t2], al, bh);
                }
            }
        }
    }

    // ---- write ctx from register accumulators ----
    #pragma unroll
    for (int t2 = 0; t2 < 2; t2++) {
        int col = i * 64 + 8 * ns + 32 * t2 + 2 * t;
        int row = m0 + 16 * mb + g;
        *(float2*)&ctx[((size_t)b * 512 + row) * 512 + col] =
            make_float2(cacc[t2][0], cacc[t2][1]);
        *(float2*)&ctx[((size_t)b * 512 + row + 8) * 512 + col] =
            make_float2(cacc[t2][2], cacc[t2][3]);
    }
}

// ---------------- launch ----------------------------------------------------
extern "C" void kernel_launch(void* const* d_in, const int* in_sizes, int n_in,
                              void* d_out, int out_size)
{
    const float* X   = (const float*)d_in[0];
    const float* w1  = (const float*)d_in[2];
    const float* b1  = (const float*)d_in[3];
    const float* g1  = (const float*)d_in[4];
    const float* be1 = (const float*)d_in[5];
    const float* m1  = (const float*)d_in[6];
    const float* v1  = (const float*)d_in[7];
    const float* w2  = (const float*)d_in[8];
    const float* b2  = (const float*)d_in[9];
    const float* g2  = (const float*)d_in[10];
    const float* be2 = (const float*)d_in[11];
    const float* m2  = (const float*)d_in[12];
    const float* v2  = (const float*)d_in[13];

    float* out  = (float*)d_out;
    float* attn = out + (size_t)4 * 512 * 512;

    float *mid, *qkv, *ctx;
    cudaGetSymbolAddress((void**)&mid, g_mid);
    cudaGetSymbolAddress((void**)&qkv, g_qkv);
    cudaGetSymbolAddress((void**)&ctx, g_ctx);

    cudaFuncSetAttribute(attn_mma_kernel, cudaFuncAttributeMaxDynamicSharedMemorySize, SMEMB);

    dim3 cb1(64, 4), cb2(32, 8);

    conv1_kernel<<<dim3(8, 128, 96), cb1>>>(X, w1, b1, g1, be1, m1, v1, mid, 0);
    conv2_kernel<<<dim3(16, 64, 12), cb2>>>(mid, w2, b2, g2, be2, m2, v2, qkv, 0);

    attn_mma_kernel<<<dim3(8, 8, 4), 512, SMEMB>>>(qkv, qkv + 1048576, qkv + 2097152, attn, ctx);

    conv1_kernel<<<dim3(8, 128, 32), cb1>>>(ctx, w1, b1, g1, be1, m1, v1, mid, 3);
    conv2_kernel<<<dim3(16, 64, 4), cb2>>>(mid, w2, b2, g2, be2, m2, v2, out, 3);
}

// round 10
// speedup vs baseline: 1.4985x; 1.0140x over previous
#include <cuda_runtime.h>
#include <cuda_bf16.h>
#include <cstdint>

#define EPSV 1e-5f

__device__ float g_mid[3 * 4 * 8 * 512 * 512];
__device__ float g_qkv[3 * 4 * 512 * 512];
__device__ float g_ctx[4 * 512 * 512];
// bf16 hi/lo packed-pair buffers (MMA-ready layouts)
__device__ uint32_t g_qh[4 * 512 * 256], g_ql[4 * 512 * 256];   // [b][m][kpair]
__device__ uint32_t g_kh[4 * 512 * 256], g_kl[4 * 512 * 256];   // [b][n][kpair]
__device__ uint32_t g_vth[4 * 8 * 64 * 256], g_vtl[4 * 8 * 64 * 256]; // [b,j][d][npair]

// ======================= conv kernels =======================================
__global__ void __launch_bounds__(256)
conv1_kernel(const float* __restrict__ xin, const float* __restrict__ w1,
             const float* __restrict__ b1, const float* __restrict__ g1,
             const float* __restrict__ be1, const float* __restrict__ m1,
             const float* __restrict__ v1, float* __restrict__ mid, int pbase)
{
    int z = blockIdx.z;
    int c = z & 7, b = (z >> 3) & 3, pl = z >> 5;
    int p = pbase + pl;
    int x = blockIdx.x * 64 + threadIdx.x;
    int y = blockIdx.y * 4 + threadIdx.y;
    int pc = p * 8 + c;
    float a  = g1[pc] * rsqrtf(v1[pc] + EPSV);
    float bb = be1[pc] + a * (b1[pc] - m1[pc]);
    const float* w  = w1 + pc * 9;
    const float* xb = xin + b * 262144;
    float s;
    if (x > 0 && x < 511 && y > 0 && y < 511) {
        const float* r0 = xb + (y - 1) * 512 + x;
        const float* r1 = r0 + 512;
        const float* r2 = r1 + 512;
        s = r0[-1] * w[0] + r0[0] * w[1] + r0[1] * w[2]
          + r1[-1] * w[3] + r1[0] * w[4] + r1[1] * w[5]
          + r2[-1] * w[6] + r2[0] * w[7] + r2[1] * w[8];
    } else {
        s = 0.f;
        #pragma unroll
        for (int ky = 0; ky < 3; ky++) {
            int yy = y + ky - 1;
            if (yy < 0 || yy > 511) continue;
            const float* row = xb + yy * 512;
            #pragma unroll
            for (int kx = 0; kx < 3; kx++) {
                int xx = x + kx - 1;
                if (xx < 0 || xx > 511) continue;
                s += row[xx] * w[ky * 3 + kx];
            }
        }
    }
    mid[(size_t)((pl * 4 + b) * 8 + c) * 262144 + y * 512 + x] = fmaxf(fmaf(a, s, bb), 0.f);
}

__global__ void __launch_bounds__(256)
conv2_kernel(const float* __restrict__ mid, const float* __restrict__ w2,
             const float* __restrict__ b2, const float* __restrict__ g2,
             const float* __restrict__ be2, const float* __restrict__ m2,
             const float* __restrict__ v2, float* __restrict__ out, int pbase)
{
    __shared__ float tile[8][10][34];
    __shared__ float ws[72];
    int z = blockIdx.z;
    int b = z & 3, pl = z >> 2, p = pbase + pl;
    int tid = threadIdx.y * 32 + threadIdx.x;
    if (tid < 72) ws[tid] = w2[p * 72 + tid];
    float a  = g2[p] * rsqrtf(v2[p] + EPSV);
    float bb = be2[p] + a * (b2[p] - m2[p]);
    int x0 = blockIdx.x * 32, y0 = blockIdx.y * 8;
    const float* in = mid + (size_t)(pl * 4 + b) * 8 * 262144;
    for (int idx = tid; idx < 8 * 10 * 34; idx += 256) {
        int c = idx / 340, r = idx % 340, yy = r / 34, xx = r % 34;
        int gy = y0 + yy - 1, gx = x0 + xx - 1;
        float vv = 0.f;
        if (gy >= 0 && gy < 512 && gx >= 0 && gx < 512)
            vv = in[(size_t)c * 262144 + gy * 512 + gx];
        tile[c][yy][xx] = vv;
    }
    __syncthreads();
    int tx = threadIdx.x, ty = threadIdx.y;
    float s = 0.f;
    #pragma unroll
    for (int c = 0; c < 8; c++)
        #pragma unroll
        for (int ky = 0; ky < 3; ky++)
            #pragma unroll
            for (int kx = 0; kx < 3; kx++)
                s = fmaf(tile[c][ty + ky][tx + kx], ws[c * 9 + ky * 3 + kx], s);
    out[(size_t)(pl * 4 + b) * 262144 + (y0 + ty) * 512 + x0 + tx] = fmaxf(fmaf(a, s, bb), 0.f);
}

// ======================= bf16 split helpers =================================
__device__ __forceinline__ uint32_t pkbf(float lo, float hi) {
    __nv_bfloat162 t = __floats2bfloat162_rn(lo, hi);
    return *reinterpret_cast<uint32_t*>(&t);
}
__device__ __forceinline__ uint32_t hipair(uint32_t u0, uint32_t u1) {
    return (u0 >> 16) | (u1 & 0xFFFF0000u);
}
__device__ __forceinline__ float hif(float x) {
    return __uint_as_float(__float_as_uint(x) & 0xFFFF0000u);
}
__device__ __forceinline__ void mma_bf16(float d[4], const uint32_t a[4],
                                         const uint32_t b[2]) {
    asm volatile(
        "mma.sync.aligned.m16n8k16.row.col.f32.bf16.bf16.f32 "
        "{%0,%1,%2,%3}, {%4,%5,%6,%7}, {%8,%9}, {%0,%1,%2,%3};"
        : "+f"(d[0]), "+f"(d[1]), "+f"(d[2]), "+f"(d[3])
        : "r"(a[0]), "r"(a[1]), "r"(a[2]), "r"(a[3]), "r"(b[0]), "r"(b[1]));
}

// ---- pre-pass: split Q (scaled 1/8) and K into hi/lo bf16 pairs ------------
__global__ void __launch_bounds__(256)
splitqk_kernel(const float* __restrict__ qkv)
{
    int it = blockIdx.x * 256 + threadIdx.x;       // 0..524287 float4 units
    bool isQ = it < 262144;
    float4 v = ((const float4*)qkv)[it];
    if (isQ) { v.x *= 0.125f; v.y *= 0.125f; v.z *= 0.125f; v.w *= 0.125f; }
    uint2 hi = make_uint2(hipair(__float_as_uint(v.x), __float_as_uint(v.y)),
                          hipair(__float_as_uint(v.z), __float_as_uint(v.w)));
    uint2 lo = make_uint2(pkbf(v.x - hif(v.x), v.y - hif(v.y)),
                          pkbf(v.z - hif(v.z), v.w - hif(v.w)));
    if (isQ) {
        *(uint2*)&g_qh[(size_t)it * 2] = hi;
        *(uint2*)&g_ql[(size_t)it * 2] = lo;
    } else {
        size_t o = (size_t)(it - 262144) * 2;
        *(uint2*)&g_kh[o] = hi;
        *(uint2*)&g_kl[o] = lo;
    }
}

// ---- pre-pass: V -> V^T[b,j][d][n] hi/lo bf16 pairs ------------------------
__global__ void __launch_bounds__(256)
splitvt_kernel(const float* __restrict__ V)
{
    int it = blockIdx.x * 256 + threadIdx.x;       // 0..131071
    int d = it & 63;
    int u = it >> 6;
    int n0 = (u & 63) * 8;
    int j  = (u >> 6) & 7;
    int b  = u >> 9;
    float vv[8];
    #pragma unroll
    for (int e = 0; e < 8; e++)
        vv[e] = V[((size_t)b * 512 + n0 + e) * 512 + j * 64 + d];
    uint32_t hw[4], lw[4];
    #pragma unroll
    for (int e = 0; e < 4; e++) {
        hw[e] = hipair(__float_as_uint(vv[2 * e]), __float_as_uint(vv[2 * e + 1]));
        lw[e] = pkbf(vv[2 * e] - hif(vv[2 * e]), vv[2 * e + 1] - hif(vv[2 * e + 1]));
    }
    size_t wbase = ((size_t)(b * 8 + j) * 64 + d) * 256 + (n0 >> 1);
    *(uint4*)&g_vth[wbase] = make_uint4(hw[0], hw[1], hw[2], hw[3]);
    *(uint4*)&g_vtl[wbase] = make_uint4(lw[0], lw[1], lw[2], lw[3]);
}

// smem (byte offsets): Ss[64][516] f32, then aliased region2, then persistent Q
#define SSTR 516
#define O_R2  132096
#define O_KH  (O_R2)                 // S phase: [128][36] words
#define O_KL  (O_R2 + 18432)
#define O_PAH (O_R2)                 // ctx phase: [64][68] words
#define O_PAL (O_R2 + 17408)
#define O_VTH (O_R2 + 34816)
#define O_VTL (O_R2 + 52224)
#define O_QH  (O_R2 + 69632)         // persistent: [64][36] words
#define O_QL  (O_QH + 9216)
#define SMEMB (O_QL + 9216)          // 220160 B

// ======================= attention via mma.sync bf16 ========================
__global__ void __launch_bounds__(512, 1)
attn_mma_kernel(const uint32_t* __restrict__ Qh, const uint32_t* __restrict__ Ql,
                const uint32_t* __restrict__ Kh, const uint32_t* __restrict__ Kl,
                const uint32_t* __restrict__ VTh, const uint32_t* __restrict__ VTl,
                float* __restrict__ attn_out, float* __restrict__ ctx)
{
    extern __shared__ char smc[];
    float* Ss = (float*)smc;
    uint32_t* KH  = (uint32_t*)(smc + O_KH);
    uint32_t* KL  = (uint32_t*)(smc + O_KL);
    uint32_t* PAH = (uint32_t*)(smc + O_PAH);
    uint32_t* PAL = (uint32_t*)(smc + O_PAL);
    uint32_t* VTH = (uint32_t*)(smc + O_VTH);
    uint32_t* VTL = (uint32_t*)(smc + O_VTL);
    uint32_t* QH  = (uint32_t*)(smc + O_QH);
    uint32_t* QL  = (uint32_t*)(smc + O_QL);

    const int tid = threadIdx.x;
    const int w = tid >> 5, lane = tid & 31;
    const int g = lane >> 2, t = lane & 3;
    const int mb = w & 3, ns = w >> 2;
    const int b = blockIdx.z, i = blockIdx.y, m0 = blockIdx.x * 64;

    // stage Q tile hi/lo (persistent)
    {
        int row = tid >> 3, p = (tid & 7) * 4;
        size_t gw = ((size_t)b * 512 + m0 + row) * 256 + i * 32 + p;
        *(uint4*)&QH[row * 36 + p] = *(const uint4*)&Qh[gw];
        *(uint4*)&QL[row * 36 + p] = *(const uint4*)&Ql[gw];
    }

    float cacc[2][4];
    #pragma unroll
    for (int a2 = 0; a2 < 2; a2++)
        #pragma unroll
        for (int c2 = 0; c2 < 4; c2++) cacc[a2][c2] = 0.f;

    for (int j = 0; j < 8; j++) {
        // ================= S = Q K^T, 4 chunks of 128 n =================
        for (int nc = 0; nc < 4; nc++) {
            __syncthreads();
            #pragma unroll
            for (int tt = 0; tt < 2; tt++) {
                int idx = tid + tt * 512;
                int row = idx >> 3, p = (idx & 7) * 4;
                size_t gw = ((size_t)b * 512 + nc * 128 + row) * 256 + j * 32 + p;
                *(uint4*)&KH[row * 36 + p] = *(const uint4*)&Kh[gw];
                *(uint4*)&KL[row * 36 + p] = *(const uint4*)&Kl[gw];
            }
            __syncthreads();

            float sacc[4][4];
            #pragma unroll
            for (int nt = 0; nt < 4; nt++)
                #pragma unroll
                for (int c2 = 0; c2 < 4; c2++) sacc[nt][c2] = 0.f;

            #pragma unroll
            for (int kc = 0; kc < 4; kc++) {
                int ab = (16 * mb + g) * 36 + kc * 8 + t;
                uint32_t ah[4] = { QH[ab], QH[ab + 288], QH[ab + 4], QH[ab + 292] };
                uint32_t al[4] = { QL[ab], QL[ab + 288], QL[ab + 4], QL[ab + 292] };
                #pragma unroll
                for (int nt = 0; nt < 4; nt++) {
                    int bb = (32 * ns + 8 * nt + g) * 36 + kc * 8 + t;
                    uint32_t bh[2] = { KH[bb], KH[bb + 4] };
                    uint32_t bl[2] = { KL[bb], KL[bb + 4] };
                    mma_bf16(sacc[nt], ah, bh);
                    mma_bf16(sacc[nt], ah, bl);
                    mma_bf16(sacc[nt], al, bh);
                }
            }
            #pragma unroll
            for (int nt = 0; nt < 4; nt++) {
                int col = nc * 128 + 32 * ns + 8 * nt + 2 * t;
                *(float2*)&Ss[(16 * mb + g) * SSTR + col] =
                    make_float2(sacc[nt][0], sacc[nt][1]);
                *(float2*)&Ss[(16 * mb + g + 8) * SSTR + col] =
                    make_float2(sacc[nt][2], sacc[nt][3]);
            }
        }
        __syncthreads();

        // ================= softmax over n, write attn ====================
        {
            float* ab = attn_out + ((((size_t)b * 8 + i) * 8 + j) * 512 + m0) * 512;
            for (int r = 4 * w; r < 4 * w + 4; r++) {
                float vals[16];
                float mx = -3.4e38f;
                #pragma unroll
                for (int tt = 0; tt < 16; tt++) {
                    vals[tt] = Ss[r * SSTR + lane + 32 * tt];
                    mx = fmaxf(mx, vals[tt]);
                }
                #pragma unroll
                for (int o = 16; o > 0; o >>= 1)
                    mx = fmaxf(mx, __shfl_xor_sync(0xffffffffu, mx, o));
                float sum = 0.f;
                #pragma unroll
                for (int tt = 0; tt < 16; tt++) { vals[tt] = __expf(vals[tt] - mx); sum += vals[tt]; }
                #pragma unroll
                for (int o = 16; o > 0; o >>= 1)
                    sum += __shfl_xor_sync(0xffffffffu, sum, o);
                float inv = 1.f / sum;
                #pragma unroll
                for (int tt = 0; tt < 16; tt++) {
                    float pv = vals[tt] * inv;
                    Ss[r * SSTR + lane + 32 * tt] = pv;
                    __stcs(&ab[(size_t)r * 512 + lane + 32 * tt], pv);
                }
            }
        }

        // ================= ctx += P V, 4 chunks of 128 n =================
        for (int vc = 0; vc < 4; vc++) {
            __syncthreads();
            // P chunk -> A layout hi/lo
            {
                int r = tid >> 3, q = (tid & 7) * 16;
                float4 p0 = *(const float4*)&Ss[r * SSTR + vc * 128 + q];
                float4 p1 = *(const float4*)&Ss[r * SSTR + vc * 128 + q + 4];
                float4 p2 = *(const float4*)&Ss[r * SSTR + vc * 128 + q + 8];
                float4 p3 = *(const float4*)&Ss[r * SSTR + vc * 128 + q + 12];
                int wi = r * 68 + (q >> 1);
                *(uint4*)&PAH[wi] = make_uint4(
                    hipair(__float_as_uint(p0.x), __float_as_uint(p0.y)),
                    hipair(__float_as_uint(p0.z), __float_as_uint(p0.w)),
                    hipair(__float_as_uint(p1.x), __float_as_uint(p1.y)),
                    hipair(__float_as_uint(p1.z), __float_as_uint(p1.w)));
                *(uint4*)&PAH[wi + 4] = make_uint4(
                    hipair(__float_as_uint(p2.x), __float_as_uint(p2.y)),
                    hipair(__float_as_uint(p2.z), __float_as_uint(p2.w)),
                    hipair(__float_as_uint(p3.x), __float_as_uint(p3.y)),
                    hipair(__float_as_uint(p3.z), __float_as_uint(p3.w)));
                *(uint4*)&PAL[wi] = make_uint4(
                    pkbf(p0.x - hif(p0.x), p0.y - hif(p0.y)),
                    pkbf(p0.z - hif(p0.z), p0.w - hif(p0.w)),
                    pkbf(p1.x - hif(p1.x), p1.y - hif(p1.y)),
                    pkbf(p1.z - hif(p1.z), p1.w - hif(p1.w)));
                *(uint4*)&PAL[wi + 4] = make_uint4(
                    pkbf(p2.x - hif(p2.x), p2.y - hif(p2.y)),
                    pkbf(p2.z - hif(p2.z), p2.w - hif(p2.w)),
                    pkbf(p3.x - hif(p3.x), p3.y - hif(p3.y)),
                    pkbf(p3.z - hif(p3.z), p3.w - hif(p3.w)));
            }
            // VT chunk staging (direct copies)
            #pragma unroll
            for (int tt = 0; tt < 2; tt++) {
                int idx = tid + tt * 512;
                int d = idx >> 4, p = (idx & 15) * 4;
                size_t gw = ((size_t)(b * 8 + j) * 64 + d) * 256 + vc * 64 + p;
                *(uint4*)&VTH[d * 68 + p] = *(const uint4*)&VTh[gw];
                *(uint4*)&VTL[d * 68 + p] = *(const uint4*)&VTl[gw];
            }
            __syncthreads();
            #pragma unroll
            for (int kc = 0; kc < 8; kc++) {
                int ab = (16 * mb + g) * 68 + kc * 8 + t;
                uint32_t ah[4] = { PAH[ab], PAH[ab + 544], PAH[ab + 4], PAH[ab + 548] };
                uint32_t al[4] = { PAL[ab], PAL[ab + 544], PAL[ab + 4], PAL[ab + 548] };
                #pragma unroll
                for (int t2 = 0; t2 < 2; t2++) {
                    int bb = (16 * ns + 8 * t2 + g) * 68 + kc * 8 + t;
                    uint32_t bh[2] = { VTH[bb], VTH[bb + 4] };
                    uint32_t bl[2] = { VTL[bb], VTL[bb + 4] };
                    mma_bf16(cacc[t2], ah, bh);
                    mma_bf16(cacc[t2], ah, bl);
                    mma_bf16(cacc[t2], al, bh);
                }
            }
        }
    }

    // ---- write ctx ----
    #pragma unroll
    for (int t2 = 0; t2 < 2; t2++) {
        int col = i * 64 + 16 * ns + 8 * t2 + 2 * t;
        int row = m0 + 16 * mb + g;
        *(float2*)&ctx[((size_t)b * 512 + row) * 512 + col] =
            make_float2(cacc[t2][0], cacc[t2][1]);
        *(float2*)&ctx[((size_t)b * 512 + row + 8) * 512 + col] =
            make_float2(cacc[t2][2], cacc[t2][3]);
    }
}

// ---------------- launch ----------------------------------------------------
extern "C" void kernel_launch(void* const* d_in, const int* in_sizes, int n_in,
                              void* d_out, int out_size)
{
    const float* X   = (const float*)d_in[0];
    const float* w1  = (const float*)d_in[2];
    const float* b1  = (const float*)d_in[3];
    const float* g1  = (const float*)d_in[4];
    const float* be1 = (const float*)d_in[5];
    const float* m1  = (const float*)d_in[6];
    const float* v1  = (const float*)d_in[7];
    const float* w2  = (const float*)d_in[8];
    const float* b2  = (const float*)d_in[9];
    const float* g2  = (const float*)d_in[10];
    const float* be2 = (const float*)d_in[11];
    const float* m2  = (const float*)d_in[12];
    const float* v2  = (const float*)d_in[13];

    float* out  = (float*)d_out;
    float* attn = out + (size_t)4 * 512 * 512;

    float *mid, *qkv, *ctx;
    uint32_t *qh, *ql, *kh, *kl, *vth, *vtl;
    cudaGetSymbolAddress((void**)&mid, g_mid);
    cudaGetSymbolAddress((void**)&qkv, g_qkv);
    cudaGetSymbolAddress((void**)&ctx, g_ctx);
    cudaGetSymbolAddress((void**)&qh, g_qh);
    cudaGetSymbolAddress((void**)&ql, g_ql);
    cudaGetSymbolAddress((void**)&kh, g_kh);
    cudaGetSymbolAddress((void**)&kl, g_kl);
    cudaGetSymbolAddress((void**)&vth, g_vth);
    cudaGetSymbolAddress((void**)&vtl, g_vtl);

    cudaFuncSetAttribute(attn_mma_kernel, cudaFuncAttributeMaxDynamicSharedMemorySize, SMEMB);

    dim3 cb1(64, 4), cb2(32, 8);

    conv1_kernel<<<dim3(8, 128, 96), cb1>>>(X, w1, b1, g1, be1, m1, v1, mid, 0);
    conv2_kernel<<<dim3(16, 64, 12), cb2>>>(mid, w2, b2, g2, be2, m2, v2, qkv, 0);

    splitqk_kernel<<<2048, 256>>>(qkv);
    splitvt_kernel<<<512, 256>>>(qkv + 2097152);

    attn_mma_kernel<<<dim3(8, 8, 4), 512, SMEMB>>>(qh, ql, kh, kl, vth, vtl, attn, ctx);

    conv1_kernel<<<dim3(8, 128, 32), cb1>>>(ctx, w1, b1, g1, be1, m1, v1, mid, 3);
    conv2_kernel<<<dim3(16, 64, 4), cb2>>>(mid, w2, b2, g2, be2, m2, v2, out, 3);
}

// round 11
// speedup vs baseline: 1.5721x; 1.0491x over previous
#include <cuda_runtime.h>
#include <cuda_bf16.h>
#include <cuda_fp16.h>
#include <cstdint>

#define EPSV 1e-5f

__device__ float g_mid[3 * 4 * 8 * 512 * 512];
__device__ float g_qkv[3 * 4 * 512 * 512];
__device__ float g_ctx[4 * 512 * 512];
// packed-pair buffers (MMA-ready layouts)
__device__ uint32_t g_qh[4 * 512 * 256], g_ql[4 * 512 * 256];   // bf16 [b][m][kpair]
__device__ uint32_t g_kh[4 * 512 * 256], g_kl[4 * 512 * 256];   // bf16 [b][n][kpair]
__device__ uint32_t g_vth[4 * 8 * 64 * 256], g_vtl[4 * 8 * 64 * 256]; // fp16 [b,j][d][npair]

// ======================= conv kernels =======================================
__global__ void __launch_bounds__(256)
conv1_kernel(const float* __restrict__ xin, const float* __restrict__ w1,
             const float* __restrict__ b1, const float* __restrict__ g1,
             const float* __restrict__ be1, const float* __restrict__ m1,
             const float* __restrict__ v1, float* __restrict__ mid, int pbase)
{
    int z = blockIdx.z;
    int c = z & 7, b = (z >> 3) & 3, pl = z >> 5;
    int p = pbase + pl;
    int x = blockIdx.x * 64 + threadIdx.x;
    int y = blockIdx.y * 4 + threadIdx.y;
    int pc = p * 8 + c;
    float a  = g1[pc] * rsqrtf(v1[pc] + EPSV);
    float bb = be1[pc] + a * (b1[pc] - m1[pc]);
    const float* w  = w1 + pc * 9;
    const float* xb = xin + b * 262144;
    float s;
    if (x > 0 && x < 511 && y > 0 && y < 511) {
        const float* r0 = xb + (y - 1) * 512 + x;
        const float* r1 = r0 + 512;
        const float* r2 = r1 + 512;
        s = r0[-1] * w[0] + r0[0] * w[1] + r0[1] * w[2]
          + r1[-1] * w[3] + r1[0] * w[4] + r1[1] * w[5]
          + r2[-1] * w[6] + r2[0] * w[7] + r2[1] * w[8];
    } else {
        s = 0.f;
        #pragma unroll
        for (int ky = 0; ky < 3; ky++) {
            int yy = y + ky - 1;
            if (yy < 0 || yy > 511) continue;
            const float* row = xb + yy * 512;
            #pragma unroll
            for (int kx = 0; kx < 3; kx++) {
                int xx = x + kx - 1;
                if (xx < 0 || xx > 511) continue;
                s += row[xx] * w[ky * 3 + kx];
            }
        }
    }
    mid[(size_t)((pl * 4 + b) * 8 + c) * 262144 + y * 512 + x] = fmaxf(fmaf(a, s, bb), 0.f);
}

__global__ void __launch_bounds__(256)
conv2_kernel(const float* __restrict__ mid, const float* __restrict__ w2,
             const float* __restrict__ b2, const float* __restrict__ g2,
             const float* __restrict__ be2, const float* __restrict__ m2,
             const float* __restrict__ v2, float* __restrict__ out, int pbase)
{
    __shared__ float tile[8][10][34];
    __shared__ float ws[72];
    int z = blockIdx.z;
    int b = z & 3, pl = z >> 2, p = pbase + pl;
    int tid = threadIdx.y * 32 + threadIdx.x;
    if (tid < 72) ws[tid] = w2[p * 72 + tid];
    float a  = g2[p] * rsqrtf(v2[p] + EPSV);
    float bb = be2[p] + a * (b2[p] - m2[p]);
    int x0 = blockIdx.x * 32, y0 = blockIdx.y * 8;
    const float* in = mid + (size_t)(pl * 4 + b) * 8 * 262144;
    for (int idx = tid; idx < 8 * 10 * 34; idx += 256) {
        int c = idx / 340, r = idx % 340, yy = r / 34, xx = r % 34;
        int gy = y0 + yy - 1, gx = x0 + xx - 1;
        float vv = 0.f;
        if (gy >= 0 && gy < 512 && gx >= 0 && gx < 512)
            vv = in[(size_t)c * 262144 + gy * 512 + gx];
        tile[c][yy][xx] = vv;
    }
    __syncthreads();
    int tx = threadIdx.x, ty = threadIdx.y;
    float s = 0.f;
    #pragma unroll
    for (int c = 0; c < 8; c++)
        #pragma unroll
        for (int ky = 0; ky < 3; ky++)
            #pragma unroll
            for (int kx = 0; kx < 3; kx++)
                s = fmaf(tile[c][ty + ky][tx + kx], ws[c * 9 + ky * 3 + kx], s);
    out[(size_t)(pl * 4 + b) * 262144 + (y0 + ty) * 512 + x0 + tx] = fmaxf(fmaf(a, s, bb), 0.f);
}

// ======================= helpers ============================================
__device__ __forceinline__ uint32_t pkbf(float lo, float hi) {
    __nv_bfloat162 t = __floats2bfloat162_rn(lo, hi);
    return *reinterpret_cast<uint32_t*>(&t);
}
__device__ __forceinline__ uint32_t pkhf(float lo, float hi) {
    __half2 t = __floats2half2_rn(lo, hi);
    return *reinterpret_cast<uint32_t*>(&t);
}
__device__ __forceinline__ uint32_t hipair(uint32_t u0, uint32_t u1) {
    return (u0 >> 16) | (u1 & 0xFFFF0000u);
}
__device__ __forceinline__ float hif(float x) {
    return __uint_as_float(__float_as_uint(x) & 0xFFFF0000u);
}
__device__ __forceinline__ float hfr(float x) {
    return __half2float(__float2half_rn(x));
}
__device__ __forceinline__ void mma_bf16(float d[4], const uint32_t a[4],
                                         const uint32_t b[2]) {
    asm volatile(
        "mma.sync.aligned.m16n8k16.row.col.f32.bf16.bf16.f32 "
        "{%0,%1,%2,%3}, {%4,%5,%6,%7}, {%8,%9}, {%0,%1,%2,%3};"
        : "+f"(d[0]), "+f"(d[1]), "+f"(d[2]), "+f"(d[3])
        : "r"(a[0]), "r"(a[1]), "r"(a[2]), "r"(a[3]), "r"(b[0]), "r"(b[1]));
}
__device__ __forceinline__ void mma_f16(float d[4], const uint32_t a[4],
                                        const uint32_t b[2]) {
    asm volatile(
        "mma.sync.aligned.m16n8k16.row.col.f32.f16.f16.f32 "
        "{%0,%1,%2,%3}, {%4,%5,%6,%7}, {%8,%9}, {%0,%1,%2,%3};"
        : "+f"(d[0]), "+f"(d[1]), "+f"(d[2]), "+f"(d[3])
        : "r"(a[0]), "r"(a[1]), "r"(a[2]), "r"(a[3]), "r"(b[0]), "r"(b[1]));
}

// ---- pre-pass: Q/K bf16 hi/lo split + V^T fp16 hi/lo, merged ---------------
__global__ void __launch_bounds__(256)
split_kernel(const float* __restrict__ qkv)
{
    int bi = blockIdx.x;
    if (bi < 2048) {
        int it = bi * 256 + threadIdx.x;           // float4 units over Q,K
        bool isQ = it < 262144;
        float4 v = ((const float4*)qkv)[it];
        if (isQ) { v.x *= 0.125f; v.y *= 0.125f; v.z *= 0.125f; v.w *= 0.125f; }
        uint2 hi = make_uint2(hipair(__float_as_uint(v.x), __float_as_uint(v.y)),
                              hipair(__float_as_uint(v.z), __float_as_uint(v.w)));
        uint2 lo = make_uint2(pkbf(v.x - hif(v.x), v.y - hif(v.y)),
                              pkbf(v.z - hif(v.z), v.w - hif(v.w)));
        if (isQ) {
            *(uint2*)&g_qh[(size_t)it * 2] = hi;
            *(uint2*)&g_ql[(size_t)it * 2] = lo;
        } else {
            size_t o = (size_t)(it - 262144) * 2;
            *(uint2*)&g_kh[o] = hi;
            *(uint2*)&g_kl[o] = lo;
        }
    } else {
        int it = (bi - 2048) * 256 + threadIdx.x;  // 0..131071
        int d = it & 63;
        int u = it >> 6;
        int n0 = (u & 63) * 8;
        int j  = (u >> 6) & 7;
        int b  = u >> 9;
        const float* V = qkv + 2097152;
        float vv[8], hv[8];
        #pragma unroll
        for (int e = 0; e < 8; e++) {
            vv[e] = V[((size_t)b * 512 + n0 + e) * 512 + j * 64 + d];
            hv[e] = hfr(vv[e]);
        }
        uint32_t hw[4], lw[4];
        #pragma unroll
        for (int e = 0; e < 4; e++) {
            hw[e] = pkhf(hv[2 * e], hv[2 * e + 1]);
            lw[e] = pkhf(vv[2 * e] - hv[2 * e], vv[2 * e + 1] - hv[2 * e + 1]);
        }
        size_t wbase = ((size_t)(b * 8 + j) * 64 + d) * 256 + (n0 >> 1);
        *(uint4*)&g_vth[wbase] = make_uint4(hw[0], hw[1], hw[2], hw[3]);
        *(uint4*)&g_vtl[wbase] = make_uint4(lw[0], lw[1], lw[2], lw[3]);
    }
}

__global__ void dummy_kernel() {}

// smem (byte offsets): Ss[64][516] f32 | region2 (phase-aliased) | persistent Q
#define SSTR 516
#define O_R2  132096
#define O_KH  (O_R2)                 // S phase: [128][36] words
#define O_KL  (O_R2 + 18432)
#define O_PA  (O_R2)                 // ctx phase: P fp16 [64][68] words
#define O_VTH (O_R2 + 17408)
#define O_VTL (O_R2 + 34816)
#define O_QH  (O_R2 + 52224)         // persistent: [64][36] words
#define O_QL  (O_QH + 9216)
#define SMEMB (O_QL + 9216)          // 202752 B

// ======================= attention via mma.sync =============================
__global__ void __launch_bounds__(512, 1)
attn_mma_kernel(const uint32_t* __restrict__ Qh, const uint32_t* __restrict__ Ql,
                const uint32_t* __restrict__ Kh, const uint32_t* __restrict__ Kl,
                const uint32_t* __restrict__ VTh, const uint32_t* __restrict__ VTl,
                float* __restrict__ attn_out, float* __restrict__ ctx)
{
    extern __shared__ char smc[];
    float* Ss = (float*)smc;
    uint32_t* KH  = (uint32_t*)(smc + O_KH);
    uint32_t* KL  = (uint32_t*)(smc + O_KL);
    uint32_t* PA  = (uint32_t*)(smc + O_PA);
    uint32_t* VTH = (uint32_t*)(smc + O_VTH);
    uint32_t* VTL = (uint32_t*)(smc + O_VTL);
    uint32_t* QH  = (uint32_t*)(smc + O_QH);
    uint32_t* QL  = (uint32_t*)(smc + O_QL);

    const int tid = threadIdx.x;
    const int w = tid >> 5, lane = tid & 31;
    const int g = lane >> 2, t = lane & 3;
    const int mb = w & 3, ns = w >> 2;
    const int b = blockIdx.z, i = blockIdx.y, m0 = blockIdx.x * 64;

    // stage Q tile hi/lo (persistent)
    {
        int row = tid >> 3, p = (tid & 7) * 4;
        size_t gw = ((size_t)b * 512 + m0 + row) * 256 + i * 32 + p;
        *(uint4*)&QH[row * 36 + p] = *(const uint4*)&Qh[gw];
        *(uint4*)&QL[row * 36 + p] = *(const uint4*)&Ql[gw];
    }

    float cacc[2][4], cacc2[2][4];
    #pragma unroll
    for (int a2 = 0; a2 < 2; a2++)
        #pragma unroll
        for (int c2 = 0; c2 < 4; c2++) { cacc[a2][c2] = 0.f; cacc2[a2][c2] = 0.f; }

    for (int j = 0; j < 8; j++) {
        // ================= S = Q K^T, 4 chunks of 128 n =================
        for (int nc = 0; nc < 4; nc++) {
            __syncthreads();
            #pragma unroll
            for (int tt = 0; tt < 2; tt++) {
                int idx = tid + tt * 512;
                int row = idx >> 3, p = (idx & 7) * 4;
                size_t gw = ((size_t)b * 512 + nc * 128 + row) * 256 + j * 32 + p;
                *(uint4*)&KH[row * 36 + p] = *(const uint4*)&Kh[gw];
                *(uint4*)&KL[row * 36 + p] = *(const uint4*)&Kl[gw];
            }
            __syncthreads();

            float sacc[4][4];
            #pragma unroll
            for (int nt = 0; nt < 4; nt++)
                #pragma unroll
                for (int c2 = 0; c2 < 4; c2++) sacc[nt][c2] = 0.f;

            #pragma unroll
            for (int kc = 0; kc < 4; kc++) {
                int ab = (16 * mb + g) * 36 + kc * 8 + t;
                uint32_t ah[4] = { QH[ab], QH[ab + 288], QH[ab + 4], QH[ab + 292] };
                uint32_t al[4] = { QL[ab], QL[ab + 288], QL[ab + 4], QL[ab + 292] };
                uint32_t bh[4][2], bl[4][2];
                #pragma unroll
                for (int nt = 0; nt < 4; nt++) {
                    int bb = (32 * ns + 8 * nt + g) * 36 + kc * 8 + t;
                    bh[nt][0] = KH[bb]; bh[nt][1] = KH[bb + 4];
                    bl[nt][0] = KL[bb]; bl[nt][1] = KL[bb + 4];
                }
                // term-major: same-accumulator reuse at distance 4
                #pragma unroll
                for (int nt = 0; nt < 4; nt++) mma_bf16(sacc[nt], ah, bh[nt]);
                #pragma unroll
                for (int nt = 0; nt < 4; nt++) mma_bf16(sacc[nt], ah, bl[nt]);
                #pragma unroll
                for (int nt = 0; nt < 4; nt++) mma_bf16(sacc[nt], al, bh[nt]);
            }
            #pragma unroll
            for (int nt = 0; nt < 4; nt++) {
                int col = nc * 128 + 32 * ns + 8 * nt + 2 * t;
                *(float2*)&Ss[(16 * mb + g) * SSTR + col] =
                    make_float2(sacc[nt][0], sacc[nt][1]);
                *(float2*)&Ss[(16 * mb + g + 8) * SSTR + col] =
                    make_float2(sacc[nt][2], sacc[nt][3]);
            }
        }
        __syncthreads();

        // ================= softmax over n, write attn ====================
        {
            float* ab = attn_out + ((((size_t)b * 8 + i) * 8 + j) * 512 + m0) * 512;
            for (int r = 4 * w; r < 4 * w + 4; r++) {
                float vals[16];
                float mx = -3.4e38f;
                #pragma unroll
                for (int tt = 0; tt < 16; tt++) {
                    vals[tt] = Ss[r * SSTR + lane + 32 * tt];
                    mx = fmaxf(mx, vals[tt]);
                }
                #pragma unroll
                for (int o = 16; o > 0; o >>= 1)
                    mx = fmaxf(mx, __shfl_xor_sync(0xffffffffu, mx, o));
                float sum = 0.f;
                #pragma unroll
                for (int tt = 0; tt < 16; tt++) { vals[tt] = __expf(vals[tt] - mx); sum += vals[tt]; }
                #pragma unroll
                for (int o = 16; o > 0; o >>= 1)
                    sum += __shfl_xor_sync(0xffffffffu, sum, o);
                float inv = 1.f / sum;
                #pragma unroll
                for (int tt = 0; tt < 16; tt++) {
                    float pv = vals[tt] * inv;
                    Ss[r * SSTR + lane + 32 * tt] = pv;
                    __stcs(&ab[(size_t)r * 512 + lane + 32 * tt], pv);
                }
            }
        }

        // ================= ctx += P V (fp16), 4 chunks of 128 n ==========
        for (int vc = 0; vc < 4; vc++) {
            __syncthreads();
            // P chunk -> fp16 A layout
            {
                int r = tid >> 3, q = (tid & 7) * 16;
                float4 p0 = *(const float4*)&Ss[r * SSTR + vc * 128 + q];
                float4 p1 = *(const float4*)&Ss[r * SSTR + vc * 128 + q + 4];
                float4 p2 = *(const float4*)&Ss[r * SSTR + vc * 128 + q + 8];
                float4 p3 = *(const float4*)&Ss[r * SSTR + vc * 128 + q + 12];
                int wi = r * 68 + (q >> 1);
                *(uint4*)&PA[wi] = make_uint4(pkhf(p0.x, p0.y), pkhf(p0.z, p0.w),
                                              pkhf(p1.x, p1.y), pkhf(p1.z, p1.w));
                *(uint4*)&PA[wi + 4] = make_uint4(pkhf(p2.x, p2.y), pkhf(p2.z, p2.w),
                                                  pkhf(p3.x, p3.y), pkhf(p3.z, p3.w));
            }
            // VT chunk staging (direct copies)
            #pragma unroll
            for (int tt = 0; tt < 2; tt++) {
                int idx = tid + tt * 512;
                int d = idx >> 4, p = (idx & 15) * 4;
                size_t gw = ((size_t)(b * 8 + j) * 64 + d) * 256 + vc * 64 + p;
                *(uint4*)&VTH[d * 68 + p] = *(const uint4*)&VTh[gw];
                *(uint4*)&VTL[d * 68 + p] = *(const uint4*)&VTl[gw];
            }
            __syncthreads();
            #pragma unroll
            for (int kc = 0; kc < 8; kc++) {
                int ab = (16 * mb + g) * 68 + kc * 8 + t;
                uint32_t pa[4] = { PA[ab], PA[ab + 544], PA[ab + 4], PA[ab + 548] };
                uint32_t vh[2][2], vl[2][2];
                #pragma unroll
                for (int t2 = 0; t2 < 2; t2++) {
                    int bb = (16 * ns + 8 * t2 + g) * 68 + kc * 8 + t;
                    vh[t2][0] = VTH[bb]; vh[t2][1] = VTH[bb + 4];
                    vl[t2][0] = VTL[bb]; vl[t2][1] = VTL[bb + 4];
                }
                mma_f16(cacc[0],  pa, vh[0]);
                mma_f16(cacc[1],  pa, vh[1]);
                mma_f16(cacc2[0], pa, vl[0]);
                mma_f16(cacc2[1], pa, vl[1]);
            }
        }
    }

    // ---- write ctx (merge hi/lo-term accumulators) ----
    #pragma unroll
    for (int t2 = 0; t2 < 2; t2++) {
        int col = i * 64 + 16 * ns + 8 * t2 + 2 * t;
        int row = m0 + 16 * mb + g;
        *(float2*)&ctx[((size_t)b * 512 + row) * 512 + col] =
            make_float2(cacc[t2][0] + cacc2[t2][0], cacc[t2][1] + cacc2[t2][1]);
        *(float2*)&ctx[((size_t)b * 512 + row + 8) * 512 + col] =
            make_float2(cacc[t2][2] + cacc2[t2][2], cacc[t2][3] + cacc2[t2][3]);
    }
}

// ---------------- launch ----------------------------------------------------
extern "C" void kernel_launch(void* const* d_in, const int* in_sizes, int n_in,
                              void* d_out, int out_size)
{
    const float* X   = (const float*)d_in[0];
    const float* w1  = (const float*)d_in[2];
    const float* b1  = (const float*)d_in[3];
    const float* g1  = (const float*)d_in[4];
    const float* be1 = (const float*)d_in[5];
    const float* m1  = (const float*)d_in[6];
    const float* v1  = (const float*)d_in[7];
    const float* w2  = (const float*)d_in[8];
    const float* b2  = (const float*)d_in[9];
    const float* g2  = (const float*)d_in[10];
    const float* be2 = (const float*)d_in[11];
    const float* m2  = (const float*)d_in[12];
    const float* v2  = (const float*)d_in[13];

    float* out  = (float*)d_out;
    float* attn = out + (size_t)4 * 512 * 512;

    float *mid, *qkv, *ctx;
    uint32_t *qh, *ql, *kh, *kl, *vth, *vtl;
    cudaGetSymbolAddress((void**)&mid, g_mid);
    cudaGetSymbolAddress((void**)&qkv, g_qkv);
    cudaGetSymbolAddress((void**)&ctx, g_ctx);
    cudaGetSymbolAddress((void**)&qh, g_qh);
    cudaGetSymbolAddress((void**)&ql, g_ql);
    cudaGetSymbolAddress((void**)&kh, g_kh);
    cudaGetSymbolAddress((void**)&kl, g_kl);
    cudaGetSymbolAddress((void**)&vth, g_vth);
    cudaGetSymbolAddress((void**)&vtl, g_vtl);

    cudaFuncSetAttribute(attn_mma_kernel, cudaFuncAttributeMaxDynamicSharedMemorySize, SMEMB);

    dim3 cb1(64, 4), cb2(32, 8);

    // 7 launches/iter; attn at idx 3 => global launch #10 (ncu capture) = attn
    conv1_kernel<<<dim3(8, 128, 96), cb1>>>(X, w1, b1, g1, be1, m1, v1, mid, 0);      // 0
    conv2_kernel<<<dim3(16, 64, 12), cb2>>>(mid, w2, b2, g2, be2, m2, v2, qkv, 0);    // 1
    split_kernel<<<2560, 256>>>(qkv);                                                 // 2
    attn_mma_kernel<<<dim3(8, 8, 4), 512, SMEMB>>>(qh, ql, kh, kl, vth, vtl, attn, ctx); // 3
    conv1_kernel<<<dim3(8, 128, 32), cb1>>>(ctx, w1, b1, g1, be1, m1, v1, mid, 3);    // 4
    conv2_kernel<<<dim3(16, 64, 4), cb2>>>(mid, w2, b2, g2, be2, m2, v2, out, 3);     // 5
    dummy_kernel<<<1, 32>>>();                                                        // 6
}